// round 15
// baseline (speedup 1.0000x reference)
#include <cuda_runtime.h>
#include <cuda_fp16.h>
#include <math_constants.h>
#include <cstdint>

#define BATCH 16
#define CDIM 256
#define HWDIM 1024
#define N_TOK 16384
#define K_CODES 8192
#define ZQ_ELEMS (BATCH*CDIM*HWDIM)
#define IX_ELEMS N_TOK

#define TILE_M 128
#define CHUNK_N 128
#define CAP 96
#define GCAP 128
#define MARGIN 1e-3f
#define ROWB 528
#define NTHREADS 512
#define ESCALE 8192.0f
#define DSCALE (-2.0f/8192.0f)
#define GRID_MAIN 148
#define NUNITS 1024                  // 128 tiles x 8 groups (8 chunks each)

#define OFF_BS 67584
#define BS_BUF 67584
#define OFF_CAND 202752
#define OFF_CNT 227328
#define OFF_SMIN 227840
#define SMEM_TOTAL 228352

__device__ __align__(16) __half g_embf[K_CODES*CDIM];   // e * 8192 in f16
__device__ float g_enorm[K_CODES];
__device__ unsigned g_min[N_TOK];                       // keyed floats
__device__ int g_cnt[N_TOK];
__device__ unsigned short g_cand[N_TOK*GCAP];

__device__ __forceinline__ uint32_t smem_u32(const void* p){
    uint32_t a;
    asm("{ .reg .u64 t; cvta.to.shared.u64 t, %1; cvt.u32.u64 %0, t; }":"=r"(a):"l"(p));
    return a;
}
__device__ __forceinline__ unsigned fkey(float f){
    unsigned b = __float_as_uint(f);
    return (b & 0x80000000u) ? ~b : (b | 0x80000000u);
}
__device__ __forceinline__ float funkey(unsigned u){
    return __uint_as_float((u & 0x80000000u) ? (u ^ 0x80000000u) : ~u);
}
#define LDM_X4(r0,r1,r2,r3,addr) \
    asm volatile("ldmatrix.sync.aligned.m8n8.x4.shared.b16 {%0,%1,%2,%3}, [%4];" \
        :"=r"(r0),"=r"(r1),"=r"(r2),"=r"(r3):"r"(addr))
#define MMA_F16ACC(c0,c1,a0,a1,a2,a3,b0,b1) \
    asm volatile("mma.sync.aligned.m16n8k16.row.col.f16.f16.f16.f16 " \
        "{%0,%1},{%2,%3,%4,%5},{%6,%7},{%0,%1};" \
        :"+r"(c0),"+r"(c1) \
        :"r"(a0),"r"(a1),"r"(a2),"r"(a3),"r"(b0),"r"(b1))
#define CP_ASYNC16(dst,src) \
    asm volatile("cp.async.cg.shared.global [%0], [%1], 16;"::"r"(dst),"l"(src))
#define CP_COMMIT() asm volatile("cp.async.commit_group;":::"memory")
#define CP_WAIT1() asm volatile("cp.async.wait_group 1;":::"memory")

// ---------- prologue: enorm + f16 cvt + per-launch state reset ----------
__global__ void prep_kernel(const float* __restrict__ emb){
    int k = blockIdx.x*blockDim.x + threadIdx.x;   // 0..8191
    const float4* p = (const float4*)(emb + (size_t)k*CDIM);
    __half2* q = (__half2*)(g_embf + (size_t)k*CDIM);
    float s = 0.f;
    #pragma unroll 8
    for(int i=0;i<64;++i){
        float4 v = p[i];
        s=__fmaf_rn(v.x,v.x,s); s=__fmaf_rn(v.y,v.y,s);
        s=__fmaf_rn(v.z,v.z,s); s=__fmaf_rn(v.w,v.w,s);
        q[i*2]   = __floats2half2_rn(v.x*ESCALE, v.y*ESCALE);
        q[i*2+1] = __floats2half2_rn(v.z*ESCALE, v.w*ESCALE);
    }
    g_enorm[k] = s;
    g_cnt[k] = 0; g_cnt[k + 8192] = 0;
    g_min[k] = 0xFFFFFFFFu; g_min[k + 8192] = 0xFFFFFFFFu;
}

// ---------- main: 148 blocks, round-14 chunk loop, gmem only at tile edges ----------
__global__ void __launch_bounds__(NTHREADS,1)
vq_main(const float* __restrict__ z){
    extern __shared__ char smem[];
    const uint32_t sb = smem_u32(smem);
    const int tid = threadIdx.x;
    const int lane = tid & 31, warp = tid >> 5;
    const int wm = warp & 3, wn = warp >> 2;      // 16 warps: 32m x 32n each
    const int g = lane >> 2, t4 = lane & 3;

    unsigned* s_min = (unsigned*)(smem + OFF_SMIN);
    int* s_cnt = (int*)(smem + OFF_CNT);
    unsigned short* s_cand = (unsigned short*)(smem + OFF_CAND);

    const int bid = blockIdx.x;
    const int us = (bid*NUNITS)/GRID_MAIN;
    const int ue = ((bid+1)*NUNITS)/GRID_MAIN;
    const int NC = (ue - us)*8;

    uint32_t a_base[2], b_base[2];
    #pragma unroll
    for(int mt=0;mt<2;++mt)
        a_base[mt] = sb + (uint32_t)((wm*32 + mt*16 + (lane & 15))*ROWB
                                     + ((lane >> 4) & 1)*16);
    #pragma unroll
    for(int nh=0;nh<2;++nh)
        b_base[nh] = sb + OFF_BS + (uint32_t)((wn*32 + nh*16 + ((lane >> 4) & 1)*8
                                     + (lane & 7))*ROWB + ((lane >> 3) & 1)*16);

    // ---- stage B for first chunk ----
    {
        int ch0 = (us & 7)*8;
        const __half* src = g_embf + (size_t)ch0*CHUNK_N*CDIM;
        #pragma unroll
        for(int i=0;i<8;++i){
            int seg = tid + i*NTHREADS;
            int n = seg >> 5, c16 = seg & 31;
            CP_ASYNC16(sb + OFF_BS + (uint32_t)(n*ROWB + c16*16),
                       src + (size_t)n*CDIM + c16*8);
        }
        CP_COMMIT();
    }

    int cur_tile = -1, m0 = 0;
    float rmv[2][2];

    for(int i=0;i<NC;++i){
        const int u = us + (i>>3);
        const int tile = u >> 3;
        const int ch = (u & 7)*8 + (i & 7);
        const int k0 = ch*CHUNK_N;
        const int buf = i & 1;

        if(i+1 < NC){
            int u1 = us + ((i+1)>>3);
            int ch1 = (u1 & 7)*8 + ((i+1)&7);
            const __half* src = g_embf + (size_t)ch1*CHUNK_N*CDIM;
            const uint32_t bdst = sb + OFF_BS + (uint32_t)((buf^1)*BS_BUF);
            #pragma unroll
            for(int j=0;j<8;++j){
                int seg = tid + j*NTHREADS;
                int n = seg >> 5, c16 = seg & 31;
                CP_ASYNC16(bdst + (uint32_t)(n*ROWB + c16*16),
                           src + (size_t)n*CDIM + c16*8);
            }
        }
        CP_COMMIT();
        CP_WAIT1();

        if(tile != cur_tile){
            __syncthreads();                       // all phase-b of prev tile done
            if(tid < 128){
                if(cur_tile >= 0){                 // dump prev tile's candidates
                    int tok = m0 + tid;
                    int cn = s_cnt[tid]; if(cn > CAP) cn = CAP;
                    int base = atomicAdd(&g_cnt[tok], cn);
                    for(int j=0;j<cn && base+j < GCAP;++j)
                        g_cand[(size_t)tok*GCAP + base + j] = s_cand[tid*CAP + j];
                }
                s_min[tid] = __ldcg(&g_min[tile*TILE_M + tid]);   // keyed snapshot
                s_cnt[tid] = 0;
            }
            cur_tile = tile;
            m0 = tile*TILE_M;
            const float* zb = z + (size_t)(m0 >> 10)*(CDIM*HWDIM) + (m0 & 1023);
            #pragma unroll
            for(int j=0;j<16;++j){
                int v = tid + j*NTHREADS;
                int c = v >> 5, m4 = (v & 31)*4;
                float4 q = *(const float4*)(zb + (size_t)c*HWDIM + m4);
                *(__half*)(smem + (m4+0)*ROWB + c*2) = __float2half_rn(q.x);
                *(__half*)(smem + (m4+1)*ROWB + c*2) = __float2half_rn(q.y);
                *(__half*)(smem + (m4+2)*ROWB + c*2) = __float2half_rn(q.z);
                *(__half*)(smem + (m4+3)*ROWB + c*2) = __float2half_rn(q.w);
            }
            #pragma unroll
            for(int mt=0;mt<2;++mt){ rmv[mt][0] = CUDART_INF_F; rmv[mt][1] = CUDART_INF_F; }
        }
        __syncthreads();

        // ---- GEMM: 32m x 32n per warp, K=256, f16 accumulate (round-14 identical) ----
        uint32_t acc[2][4][2];
        #pragma unroll
        for(int mt=0;mt<2;++mt)
            #pragma unroll
            for(int nt=0;nt<4;++nt){ acc[mt][nt][0] = 0u; acc[mt][nt][1] = 0u; }

        const uint32_t boff = (uint32_t)(buf*BS_BUF);
        #pragma unroll 4
        for(int ks=0; ks<16; ++ks){
            const uint32_t koff = (uint32_t)(ks*32);
            uint32_t a[2][4], bq[2][4];
            LDM_X4(a[0][0],a[0][1],a[0][2],a[0][3], a_base[0] + koff);
            LDM_X4(a[1][0],a[1][1],a[1][2],a[1][3], a_base[1] + koff);
            LDM_X4(bq[0][0],bq[0][1],bq[0][2],bq[0][3], b_base[0] + boff + koff);
            LDM_X4(bq[1][0],bq[1][1],bq[1][2],bq[1][3], b_base[1] + boff + koff);
            #pragma unroll
            for(int mt=0;mt<2;++mt)
                #pragma unroll
                for(int nt=0;nt<4;++nt)
                    MMA_F16ACC(acc[mt][nt][0], acc[mt][nt][1],
                               a[mt][0],a[mt][1],a[mt][2],a[mt][3],
                               bq[nt>>1][(nt&1)*2], bq[nt>>1][(nt&1)*2+1]);
        }

        // ---- phase a: d = en + DSCALE*S, chunk min, record-improve atomics ----
        float en0[4], en1[4];
        #pragma unroll
        for(int nt=0;nt<4;++nt){
            int nb = k0 + wn*32 + nt*8 + 2*t4;
            en0[nt] = __ldg(&g_enorm[nb]); en1[nt] = __ldg(&g_enorm[nb+1]);
        }
        float dv[2][4][4];
        float cmin[2][2];
        #pragma unroll
        for(int mt=0;mt<2;++mt)
            #pragma unroll
            for(int h=0;h<2;++h){
                float cm = CUDART_INF_F;
                #pragma unroll
                for(int nt=0;nt<4;++nt){
                    float2 p = __half22float2(*(__half2*)&acc[mt][nt][h]);
                    float d0 = __fmaf_rn(DSCALE, p.x, en0[nt]);
                    float d1 = __fmaf_rn(DSCALE, p.y, en1[nt]);
                    dv[mt][nt][2*h] = d0; dv[mt][nt][2*h+1] = d1;
                    if(d0 < cm) cm = d0;
                    if(d1 < cm) cm = d1;
                }
                cmin[mt][h] = cm;
                if(cm < rmv[mt][h]){
                    rmv[mt][h] = cm;
                    unsigned key = fkey(cm);
                    atomicMin(&s_min[wm*32 + mt*16 + g + h*8], key);
                    atomicMin(&g_min[m0 + wm*32 + mt*16 + g + h*8], key);  // fire-forget
                }
            }
        __syncthreads();

        // ---- phase b: push candidates within margin (round-14 identical) ----
        #pragma unroll
        for(int mt=0;mt<2;++mt)
            #pragma unroll
            for(int h=0;h<2;++h){
                int m = wm*32 + mt*16 + g + h*8;
                float thr = funkey(s_min[m]) + MARGIN;
                if(cmin[mt][h] <= thr){
                    #pragma unroll
                    for(int nt=0;nt<4;++nt){
                        #pragma unroll
                        for(int q=0;q<2;++q){
                            float d = dv[mt][nt][2*h+q];
                            if(d <= thr){
                                int slot = atomicAdd(&s_cnt[m], 1);
                                if(slot < CAP)
                                    s_cand[m*CAP + slot] =
                                        (unsigned short)(k0 + wn*32 + nt*8 + 2*t4 + q);
                            }
                        }
                    }
                }
            }
    }

    // ---- final dump ----
    __syncthreads();
    if(cur_tile >= 0 && tid < 128){
        int tok = m0 + tid;
        int cn = s_cnt[tid]; if(cn > CAP) cn = CAP;
        int base = atomicAdd(&g_cnt[tok], cn);
        for(int j=0;j<cn && base+j < GCAP;++j)
            g_cand[(size_t)tok*GCAP + base + j] = s_cand[tid*CAP + j];
    }
}

// ---------- finish: exact fp32 rescore + fused outputs (round-12 verified) ----------
#define SMEM_FIN (128*257*4 + 512)
__global__ void __launch_bounds__(256,1)
finish_kernel(const float* __restrict__ z, const float* __restrict__ emb,
              float* __restrict__ out, int zq_off, int loss_off, int idx_off){
    extern __shared__ char smem[];
    float* zf = (float*)smem;
    int* s_idx = (int*)(smem + 128*257*4);
    const int tid = threadIdx.x;
    const int m0 = blockIdx.x*TILE_M;
    const int b = m0 >> 10, hw0 = m0 & 1023;
    const float* zb = z + (size_t)b*(CDIM*HWDIM) + hw0;

    #pragma unroll
    for(int i=0;i<32;++i){
        int v = tid + i*256;
        int c = v >> 5, m4 = (v & 31)*4;
        float4 q = *(const float4*)(zb + (size_t)c*HWDIM + m4);
        zf[(m4+0)*257 + c] = q.x; zf[(m4+1)*257 + c] = q.y;
        zf[(m4+2)*257 + c] = q.z; zf[(m4+3)*257 + c] = q.w;
    }
    __syncthreads();

    if(tid < 128){
        int n = m0 + tid;
        float zn = 0.f;
        #pragma unroll 8
        for(int c=0;c<CDIM;++c){
            float v = zf[tid*257 + c];
            zn = __fmaf_rn(v, v, zn);
        }
        int cn = g_cnt[n]; if(cn > GCAP) cn = GCAP;
        float best = CUDART_INF_F; int bi = 0x7FFFFFFF;
        for(int i=0;i<cn;++i){
            int k = (int)g_cand[(size_t)n*GCAP + i];
            const float* er = emb + (size_t)k*CDIM;
            float acc2 = 0.f;
            #pragma unroll 8
            for(int c=0;c<CDIM;++c)
                acc2 = __fmaf_rn(zf[tid*257 + c], er[c], acc2);
            float dd = __fsub_rn(__fadd_rn(zn, g_enorm[k]), __fmul_rn(2.f, acc2));
            if(dd < best || (dd == best && k < bi)){ best = dd; bi = k; }
        }
        s_idx[tid] = bi;
    }
    __syncthreads();

    const int m = tid & 127;
    const int idxm = s_idx[m];
    #pragma unroll 2
    for(int i=0;i<128;++i){
        int c = 2*i + (tid >> 7);
        float e  = __ldg(&emb[(size_t)idxm*CDIM + c]);
        float zv = zf[m*257 + c];
        float dq = __fsub_rn(e, zv);
        float zq = __fadd_rn(zv, dq);
        float d2 = __fmul_rn(dq, dq);
        float loss = __fadd_rn(__fmul_rn(0.25f, d2), d2);
        if(zq_off >= 0)
            out[(size_t)zq_off + (size_t)b*(CDIM*HWDIM) + (size_t)c*HWDIM + hw0 + m] = zq;
        zf[m*257 + c] = loss;
    }
    __syncthreads();

    if(loss_off >= 0){
        #pragma unroll 4
        for(int mm=0;mm<128;++mm)
            out[(size_t)loss_off + (size_t)(m0+mm)*CDIM + tid] = zf[mm*257 + tid];
    }
    if(idx_off >= 0 && tid < 128)
        out[(size_t)idx_off + m0 + tid] = (float)s_idx[tid];
}

extern "C" void kernel_launch(void* const* d_in, const int* in_sizes, int n_in,
                              void* d_out, int out_size){
    const float* z   = (const float*)d_in[0];
    const float* emb = (const float*)d_in[1];
    if(n_in >= 2 && in_sizes[0] == K_CODES*CDIM && in_sizes[1] == ZQ_ELEMS){
        z = (const float*)d_in[1]; emb = (const float*)d_in[0];
    }
    float* out = (float*)d_out;

    prep_kernel<<<K_CODES/256, 256>>>(emb);

    cudaFuncSetAttribute(vq_main, cudaFuncAttributeMaxDynamicSharedMemorySize, SMEM_TOTAL);
    vq_main<<<GRID_MAIN, NTHREADS, SMEM_TOTAL>>>(z);

    int zq_off=-1, loss_off=-1, idx_off=-1;
    if(out_size == 2*ZQ_ELEMS + IX_ELEMS){ zq_off=0; loss_off=ZQ_ELEMS; idx_off=2*ZQ_ELEMS; }
    else if(out_size == 2*ZQ_ELEMS){ zq_off=0; loss_off=ZQ_ELEMS; }
    else if(out_size == ZQ_ELEMS + IX_ELEMS){ zq_off=0; idx_off=ZQ_ELEMS; }
    else if(out_size == ZQ_ELEMS){ zq_off=0; }
    else if(out_size == IX_ELEMS){ idx_off=0; }
    else{
        int rem = out_size;
        if(rem >= ZQ_ELEMS){ zq_off=0; rem -= ZQ_ELEMS; }
        if(rem >= ZQ_ELEMS){ loss_off=ZQ_ELEMS; rem -= ZQ_ELEMS; }
        if(rem >= IX_ELEMS){ idx_off = out_size - IX_ELEMS; }
    }
    cudaFuncSetAttribute(finish_kernel, cudaFuncAttributeMaxDynamicSharedMemorySize, SMEM_FIN);
    finish_kernel<<<N_TOK/TILE_M, 256, SMEM_FIN>>>(z, emb, out, zq_off, loss_off, idx_off);
}

// round 16
// speedup vs baseline: 1.0592x; 1.0592x over previous
#include <cuda_runtime.h>
#include <cuda_fp16.h>
#include <math_constants.h>
#include <cstdint>

#define BATCH 16
#define CDIM 256
#define HWDIM 1024
#define N_TOK 16384
#define K_CODES 8192
#define ZQ_ELEMS (BATCH*CDIM*HWDIM)
#define IX_ELEMS N_TOK

#define TILE_M 128
#define CHUNK_N 128
#define NCHUNK 64
#define CAP 96
#define MARGIN 1e-3f
#define ROWB 528
#define NTHREADS 512
#define ESCALE 8192.0f
#define DSCALE (-2.0f/8192.0f)

#define OFF_BS 67584
#define BS_BUF 67584
#define OFF_CAND 202752
#define OFF_CNT 227328
#define OFF_SMIN 227840
#define SMEM_TOTAL 228352

__device__ __align__(16) __half g_embf[K_CODES*CDIM];   // e * 8192 in f16
__device__ float g_enorm[K_CODES];

__device__ __forceinline__ uint32_t smem_u32(const void* p){
    uint32_t a;
    asm("{ .reg .u64 t; cvta.to.shared.u64 t, %1; cvt.u32.u64 %0, t; }":"=r"(a):"l"(p));
    return a;
}
__device__ __forceinline__ unsigned fkey(float f){
    unsigned b = __float_as_uint(f);
    return (b & 0x80000000u) ? ~b : (b | 0x80000000u);
}
__device__ __forceinline__ float funkey(unsigned u){
    return __uint_as_float((u & 0x80000000u) ? (u ^ 0x80000000u) : ~u);
}
#define LDM_X4(r0,r1,r2,r3,addr) \
    asm volatile("ldmatrix.sync.aligned.m8n8.x4.shared.b16 {%0,%1,%2,%3}, [%4];" \
        :"=r"(r0),"=r"(r1),"=r"(r2),"=r"(r3):"r"(addr))
#define MMA_F16ACC(c0,c1,a0,a1,a2,a3,b0,b1) \
    asm volatile("mma.sync.aligned.m16n8k16.row.col.f16.f16.f16.f16 " \
        "{%0,%1},{%2,%3,%4,%5},{%6,%7},{%0,%1};" \
        :"+r"(c0),"+r"(c1) \
        :"r"(a0),"r"(a1),"r"(a2),"r"(a3),"r"(b0),"r"(b1))
#define CP_ASYNC16(dst,src) \
    asm volatile("cp.async.cg.shared.global [%0], [%1], 16;"::"r"(dst),"l"(src))
#define CP_COMMIT() asm volatile("cp.async.commit_group;":::"memory")
#define CP_WAIT1() asm volatile("cp.async.wait_group 1;":::"memory")

// ---------- prologue: enorm (exact serial FMA) + f16 cvt, uint4 stores ----------
__global__ void prep_kernel(const float* __restrict__ emb){
    int k = blockIdx.x*blockDim.x + threadIdx.x;
    const float4* p = (const float4*)(emb + (size_t)k*CDIM);
    uint4* q = (uint4*)(g_embf + (size_t)k*CDIM);
    float s = 0.f;
    #pragma unroll 4
    for(int i=0;i<32;++i){
        float4 v0 = p[2*i], v1 = p[2*i+1];
        s=__fmaf_rn(v0.x,v0.x,s); s=__fmaf_rn(v0.y,v0.y,s);
        s=__fmaf_rn(v0.z,v0.z,s); s=__fmaf_rn(v0.w,v0.w,s);
        s=__fmaf_rn(v1.x,v1.x,s); s=__fmaf_rn(v1.y,v1.y,s);
        s=__fmaf_rn(v1.z,v1.z,s); s=__fmaf_rn(v1.w,v1.w,s);
        __half2 h0 = __floats2half2_rn(v0.x*ESCALE, v0.y*ESCALE);
        __half2 h1 = __floats2half2_rn(v0.z*ESCALE, v0.w*ESCALE);
        __half2 h2 = __floats2half2_rn(v1.x*ESCALE, v1.y*ESCALE);
        __half2 h3 = __floats2half2_rn(v1.z*ESCALE, v1.w*ESCALE);
        uint4 o;
        o.x = *(uint32_t*)&h0; o.y = *(uint32_t*)&h1;
        o.z = *(uint32_t*)&h2; o.w = *(uint32_t*)&h3;
        q[i] = o;
    }
    g_enorm[k] = s;
}

// ---------- main: round-14 HMMA loop, merged single-barrier epilogue ----------
__global__ void __launch_bounds__(NTHREADS,1)
vq_main(const float* __restrict__ z, const float* __restrict__ emb,
        float* __restrict__ out, int zq_off, int loss_off, int idx_off){
    extern __shared__ char smem[];
    const uint32_t sb = smem_u32(smem);
    const int tid = threadIdx.x;
    const int lane = tid & 31, warp = tid >> 5;
    const int wm = warp & 3, wn = warp >> 2;      // 16 warps: 32m x 32n each
    const int g = lane >> 2, t4 = lane & 3;
    const int m0 = blockIdx.x*TILE_M;
    const int b = m0 >> 10, hw0 = m0 & 1023;

    unsigned* s_min = (unsigned*)(smem + OFF_SMIN);
    int* s_cnt = (int*)(smem + OFF_CNT);
    unsigned short* s_cand = (unsigned short*)(smem + OFF_CAND);
    if(tid < 128){ s_min[tid] = 0xFFFFFFFFu; s_cnt[tid] = 0; }

    // ---- z tile -> f16 A ----
    const float* zb = z + (size_t)b*(CDIM*HWDIM) + hw0;
    #pragma unroll
    for(int i=0;i<16;++i){
        int v = tid + i*NTHREADS;
        int c = v >> 5, m4 = (v & 31)*4;
        float4 q = *(const float4*)(zb + (size_t)c*HWDIM + m4);
        *(__half*)(smem + (m4+0)*ROWB + c*2) = __float2half_rn(q.x);
        *(__half*)(smem + (m4+1)*ROWB + c*2) = __float2half_rn(q.y);
        *(__half*)(smem + (m4+2)*ROWB + c*2) = __float2half_rn(q.z);
        *(__half*)(smem + (m4+3)*ROWB + c*2) = __float2half_rn(q.w);
    }

    // ---- stage chunk 0 ----
    {
        const __half* src = g_embf;
        #pragma unroll
        for(int i=0;i<8;++i){
            int seg = tid + i*NTHREADS;
            int n = seg >> 5, c16 = seg & 31;
            CP_ASYNC16(sb + OFF_BS + (uint32_t)(n*ROWB + c16*16),
                       src + (size_t)n*CDIM + c16*8);
        }
        CP_COMMIT();
    }

    uint32_t a_base[2], b_base[2];
    #pragma unroll
    for(int mt=0;mt<2;++mt)
        a_base[mt] = sb + (uint32_t)((wm*32 + mt*16 + (lane & 15))*ROWB
                                     + ((lane >> 4) & 1)*16);
    #pragma unroll
    for(int nh=0;nh<2;++nh)
        b_base[nh] = sb + OFF_BS + (uint32_t)((wn*32 + nh*16 + ((lane >> 4) & 1)*8
                                     + (lane & 7))*ROWB + ((lane >> 3) & 1)*16);

    float rmv[2][2] = {{CUDART_INF_F, CUDART_INF_F},{CUDART_INF_F, CUDART_INF_F}};

    for(int ch=0; ch<NCHUNK; ++ch){
        const int buf = ch & 1;
        const int k0 = ch*CHUNK_N;
        if(ch+1 < NCHUNK){
            const __half* src = g_embf + (size_t)(ch+1)*CHUNK_N*CDIM;
            const uint32_t bdst = sb + OFF_BS + (uint32_t)((buf^1)*BS_BUF);
            #pragma unroll
            for(int i=0;i<8;++i){
                int seg = tid + i*NTHREADS;
                int n = seg >> 5, c16 = seg & 31;
                CP_ASYNC16(bdst + (uint32_t)(n*ROWB + c16*16),
                           src + (size_t)n*CDIM + c16*8);
            }
        }
        CP_COMMIT();
        CP_WAIT1();
        __syncthreads();                          // single barrier per chunk

        // ---- GEMM: 32m x 32n per warp, K=256, f16 accumulate ----
        uint32_t acc[2][4][2];
        #pragma unroll
        for(int mt=0;mt<2;++mt)
            #pragma unroll
            for(int nt=0;nt<4;++nt){ acc[mt][nt][0] = 0u; acc[mt][nt][1] = 0u; }

        const uint32_t boff = (uint32_t)(buf*BS_BUF);
        #pragma unroll 4
        for(int ks=0; ks<16; ++ks){
            const uint32_t koff = (uint32_t)(ks*32);
            uint32_t a[2][4], bq[2][4];
            LDM_X4(a[0][0],a[0][1],a[0][2],a[0][3], a_base[0] + koff);
            LDM_X4(a[1][0],a[1][1],a[1][2],a[1][3], a_base[1] + koff);
            LDM_X4(bq[0][0],bq[0][1],bq[0][2],bq[0][3], b_base[0] + boff + koff);
            LDM_X4(bq[1][0],bq[1][1],bq[1][2],bq[1][3], b_base[1] + boff + koff);
            #pragma unroll
            for(int mt=0;mt<2;++mt)
                #pragma unroll
                for(int nt=0;nt<4;++nt)
                    MMA_F16ACC(acc[mt][nt][0], acc[mt][nt][1],
                               a[mt][0],a[mt][1],a[mt][2],a[mt][3],
                               bq[nt>>1][(nt&1)*2], bq[nt>>1][(nt&1)*2+1]);
        }

        // ---- merged epilogue: d, min update, stale-tolerant margin push ----
        float en0[4], en1[4];
        #pragma unroll
        for(int nt=0;nt<4;++nt){
            int nb = k0 + wn*32 + nt*8 + 2*t4;
            en0[nt] = __ldg(&g_enorm[nb]); en1[nt] = __ldg(&g_enorm[nb+1]);
        }
        #pragma unroll
        for(int mt=0;mt<2;++mt)
            #pragma unroll
            for(int h=0;h<2;++h){
                float dvv[8];
                float cm = CUDART_INF_F;
                #pragma unroll
                for(int nt=0;nt<4;++nt){
                    float2 p = __half22float2(*(__half2*)&acc[mt][nt][h]);
                    float d0 = __fmaf_rn(DSCALE, p.x, en0[nt]);
                    float d1 = __fmaf_rn(DSCALE, p.y, en1[nt]);
                    dvv[2*nt] = d0; dvv[2*nt+1] = d1;
                    if(d0 < cm) cm = d0;
                    if(d1 < cm) cm = d1;
                }
                int m = wm*32 + mt*16 + g + h*8;
                if(cm < rmv[mt][h]){
                    rmv[mt][h] = cm;
                    atomicMin(&s_min[m], fkey(cm));
                }
                // stale-tolerant threshold: >= true min + MARGIN always
                float thr = fminf(funkey(s_min[m]), rmv[mt][h]) + MARGIN;
                if(cm <= thr){
                    #pragma unroll
                    for(int nt=0;nt<4;++nt){
                        #pragma unroll
                        for(int q=0;q<2;++q){
                            if(dvv[2*nt+q] <= thr){
                                int slot = atomicAdd(&s_cnt[m], 1);
                                if(slot < CAP)
                                    s_cand[m*CAP + slot] =
                                        (unsigned short)(k0 + wn*32 + nt*8 + 2*t4 + q);
                            }
                        }
                    }
                }
            }
    }
    __syncthreads();

    // ---- reload exact fp32 z tile into freed A/B smem ----
    float* zf = (float*)smem;
    #pragma unroll
    for(int i=0;i<16;++i){
        int v = tid + i*NTHREADS;
        int c = v >> 5, m4 = (v & 31)*4;
        float4 q = *(const float4*)(zb + (size_t)c*HWDIM + m4);
        zf[(m4+0)*257 + c] = q.x; zf[(m4+1)*257 + c] = q.y;
        zf[(m4+2)*257 + c] = q.z; zf[(m4+3)*257 + c] = q.w;
    }
    __syncthreads();

    // ---- exact fp32 rescore (serial-FMA rounding == reference path) ----
    int* s_idx = (int*)(smem + OFF_SMIN);    // s_min dead after loop
    if(tid < 128){
        float zn = 0.f;
        #pragma unroll 8
        for(int c=0;c<CDIM;++c){
            float v = zf[tid*257 + c];
            zn = __fmaf_rn(v, v, zn);
        }
        int cn = s_cnt[tid]; if(cn > CAP) cn = CAP;
        float best = CUDART_INF_F; int bi = 0x7FFFFFFF;
        for(int i=0;i<cn;++i){
            int k = (int)s_cand[tid*CAP + i];
            const float* er = emb + (size_t)k*CDIM;
            float acc2 = 0.f;
            #pragma unroll 8
            for(int c=0;c<CDIM;++c)
                acc2 = __fmaf_rn(zf[tid*257 + c], er[c], acc2);
            float dd = __fsub_rn(__fadd_rn(zn, g_enorm[k]), __fmul_rn(2.f, acc2));
            if(dd < best || (dd == best && k < bi)){ best = dd; bi = k; }
        }
        s_idx[tid] = bi;
    }
    __syncthreads();

    // ---- fused outputs (round-14 verified) ----
    {
        const int m = tid & 127;
        const int cq = tid >> 7;                 // 0..3
        const int idxm = s_idx[m];
        #pragma unroll 2
        for(int i=0;i<64;++i){
            int c = 4*i + cq;
            float e  = __ldg(&emb[(size_t)idxm*CDIM + c]);
            float zv = zf[m*257 + c];
            float dq = __fsub_rn(e, zv);
            float zq = __fadd_rn(zv, dq);
            float d2 = __fmul_rn(dq, dq);
            float loss = __fadd_rn(__fmul_rn(0.25f, d2), d2);
            if(zq_off >= 0)
                out[(size_t)zq_off + (size_t)b*(CDIM*HWDIM) + (size_t)c*HWDIM + hw0 + m] = zq;
            zf[m*257 + c] = loss;
        }
    }
    __syncthreads();

    if(loss_off >= 0){
        const int c = tid & 255;
        const int mh = tid >> 8;                 // 0..1
        #pragma unroll 4
        for(int j=0;j<64;++j){
            int mm = 2*j + mh;
            out[(size_t)loss_off + (size_t)(m0+mm)*CDIM + c] = zf[mm*257 + c];
        }
    }
    if(idx_off >= 0 && tid < 128)
        out[(size_t)idx_off + m0 + tid] = (float)s_idx[tid];
}

extern "C" void kernel_launch(void* const* d_in, const int* in_sizes, int n_in,
                              void* d_out, int out_size){
    const float* z   = (const float*)d_in[0];
    const float* emb = (const float*)d_in[1];
    if(n_in >= 2 && in_sizes[0] == K_CODES*CDIM && in_sizes[1] == ZQ_ELEMS){
        z = (const float*)d_in[1]; emb = (const float*)d_in[0];
    }
    float* out = (float*)d_out;

    int zq_off=-1, loss_off=-1, idx_off=-1;
    if(out_size == 2*ZQ_ELEMS + IX_ELEMS){ zq_off=0; loss_off=ZQ_ELEMS; idx_off=2*ZQ_ELEMS; }
    else if(out_size == 2*ZQ_ELEMS){ zq_off=0; loss_off=ZQ_ELEMS; }
    else if(out_size == ZQ_ELEMS + IX_ELEMS){ zq_off=0; idx_off=ZQ_ELEMS; }
    else if(out_size == ZQ_ELEMS){ zq_off=0; }
    else if(out_size == IX_ELEMS){ idx_off=0; }
    else{
        int rem = out_size;
        if(rem >= ZQ_ELEMS){ zq_off=0; rem -= ZQ_ELEMS; }
        if(rem >= ZQ_ELEMS){ loss_off=ZQ_ELEMS; rem -= ZQ_ELEMS; }
        if(rem >= IX_ELEMS){ idx_off = out_size - IX_ELEMS; }
    }

    prep_kernel<<<K_CODES/256, 256>>>(emb);

    cudaFuncSetAttribute(vq_main, cudaFuncAttributeMaxDynamicSharedMemorySize, SMEM_TOTAL);
    vq_main<<<N_TOK/TILE_M, NTHREADS, SMEM_TOTAL>>>(z, emb, out, zq_off, loss_off, idx_off);
}

// round 17
// speedup vs baseline: 1.1503x; 1.0860x over previous
#include <cuda_runtime.h>
#include <cuda_fp16.h>
#include <math_constants.h>
#include <cstdint>

#define BATCH 16
#define CDIM 256
#define HWDIM 1024
#define N_TOK 16384
#define K_CODES 8192
#define ZQ_ELEMS (BATCH*CDIM*HWDIM)
#define IX_ELEMS N_TOK

#define TILE_M 128
#define CHUNK_N 128
#define NCHUNK 64
#define CAP 96
#define MARGIN 1e-3f
#define ROWB 528
#define NTHREADS 512
#define ESCALE 8192.0f
#define DSCALE (-2.0f/8192.0f)

#define OFF_BS 67584
#define BS_BUF 67584
#define OFF_CAND 202752
#define OFF_CNT 227328
#define OFF_SMIN 227840
#define SMEM_TOTAL 228352

__device__ __align__(16) __half g_embf[K_CODES*CDIM];   // e * 8192 in f16
__device__ float g_enorm[K_CODES];

__device__ __forceinline__ uint32_t smem_u32(const void* p){
    uint32_t a;
    asm("{ .reg .u64 t; cvta.to.shared.u64 t, %1; cvt.u32.u64 %0, t; }":"=r"(a):"l"(p));
    return a;
}
__device__ __forceinline__ unsigned fkey(float f){
    unsigned b = __float_as_uint(f);
    return (b & 0x80000000u) ? ~b : (b | 0x80000000u);
}
__device__ __forceinline__ float funkey(unsigned u){
    return __uint_as_float((u & 0x80000000u) ? (u ^ 0x80000000u) : ~u);
}
#define LDM_X4(r0,r1,r2,r3,addr) \
    asm volatile("ldmatrix.sync.aligned.m8n8.x4.shared.b16 {%0,%1,%2,%3}, [%4];" \
        :"=r"(r0),"=r"(r1),"=r"(r2),"=r"(r3):"r"(addr))
#define MMA_F16ACC(c0,c1,a0,a1,a2,a3,b0,b1) \
    asm volatile("mma.sync.aligned.m16n8k16.row.col.f16.f16.f16.f16 " \
        "{%0,%1},{%2,%3,%4,%5},{%6,%7},{%0,%1};" \
        :"+r"(c0),"+r"(c1) \
        :"r"(a0),"r"(a1),"r"(a2),"r"(a3),"r"(b0),"r"(b1))
#define CP_ASYNC16(dst,src) \
    asm volatile("cp.async.cg.shared.global [%0], [%1], 16;"::"r"(dst),"l"(src))
#define CP_COMMIT() asm volatile("cp.async.commit_group;":::"memory")
#define CP_WAIT1() asm volatile("cp.async.wait_group 1;":::"memory")

// ---------- prologue: enorm (exact serial FMA) + f16 cvt, uint4 stores ----------
__global__ void prep_kernel(const float* __restrict__ emb){
    int k = blockIdx.x*blockDim.x + threadIdx.x;
    const float4* p = (const float4*)(emb + (size_t)k*CDIM);
    uint4* q = (uint4*)(g_embf + (size_t)k*CDIM);
    float s = 0.f;
    #pragma unroll 4
    for(int i=0;i<32;++i){
        float4 v0 = p[2*i], v1 = p[2*i+1];
        s=__fmaf_rn(v0.x,v0.x,s); s=__fmaf_rn(v0.y,v0.y,s);
        s=__fmaf_rn(v0.z,v0.z,s); s=__fmaf_rn(v0.w,v0.w,s);
        s=__fmaf_rn(v1.x,v1.x,s); s=__fmaf_rn(v1.y,v1.y,s);
        s=__fmaf_rn(v1.z,v1.z,s); s=__fmaf_rn(v1.w,v1.w,s);
        __half2 h0 = __floats2half2_rn(v0.x*ESCALE, v0.y*ESCALE);
        __half2 h1 = __floats2half2_rn(v0.z*ESCALE, v0.w*ESCALE);
        __half2 h2 = __floats2half2_rn(v1.x*ESCALE, v1.y*ESCALE);
        __half2 h3 = __floats2half2_rn(v1.z*ESCALE, v1.w*ESCALE);
        uint4 o;
        o.x = *(uint32_t*)&h0; o.y = *(uint32_t*)&h1;
        o.z = *(uint32_t*)&h2; o.w = *(uint32_t*)&h3;
        q[i] = o;
    }
    g_enorm[k] = s;
}

// ---------- main: round-14 HMMA loop + exact rescore + fused outputs ----------
__global__ void __launch_bounds__(NTHREADS,1)
vq_main(const float* __restrict__ z, const float* __restrict__ emb,
        float* __restrict__ out, int zq_off, int loss_off, int idx_off){
    extern __shared__ char smem[];
    const uint32_t sb = smem_u32(smem);
    const int tid = threadIdx.x;
    const int lane = tid & 31, warp = tid >> 5;
    const int wm = warp & 3, wn = warp >> 2;      // 16 warps: 32m x 32n each
    const int g = lane >> 2, t4 = lane & 3;
    const int m0 = blockIdx.x*TILE_M;
    const int b = m0 >> 10, hw0 = m0 & 1023;

    unsigned* s_min = (unsigned*)(smem + OFF_SMIN);
    int* s_cnt = (int*)(smem + OFF_CNT);
    unsigned short* s_cand = (unsigned short*)(smem + OFF_CAND);
    if(tid < 128){ s_min[tid] = 0xFFFFFFFFu; s_cnt[tid] = 0; }

    // ---- z tile -> f16 A ----
    const float* zb = z + (size_t)b*(CDIM*HWDIM) + hw0;
    #pragma unroll
    for(int i=0;i<16;++i){
        int v = tid + i*NTHREADS;
        int c = v >> 5, m4 = (v & 31)*4;
        float4 q = *(const float4*)(zb + (size_t)c*HWDIM + m4);
        *(__half*)(smem + (m4+0)*ROWB + c*2) = __float2half_rn(q.x);
        *(__half*)(smem + (m4+1)*ROWB + c*2) = __float2half_rn(q.y);
        *(__half*)(smem + (m4+2)*ROWB + c*2) = __float2half_rn(q.z);
        *(__half*)(smem + (m4+3)*ROWB + c*2) = __float2half_rn(q.w);
    }

    // ---- stage chunk 0 ----
    {
        const __half* src = g_embf;
        #pragma unroll
        for(int i=0;i<8;++i){
            int seg = tid + i*NTHREADS;
            int n = seg >> 5, c16 = seg & 31;
            CP_ASYNC16(sb + OFF_BS + (uint32_t)(n*ROWB + c16*16),
                       src + (size_t)n*CDIM + c16*8);
        }
        CP_COMMIT();
    }

    uint32_t a_base[2], b_base[2];
    #pragma unroll
    for(int mt=0;mt<2;++mt)
        a_base[mt] = sb + (uint32_t)((wm*32 + mt*16 + (lane & 15))*ROWB
                                     + ((lane >> 4) & 1)*16);
    #pragma unroll
    for(int nh=0;nh<2;++nh)
        b_base[nh] = sb + OFF_BS + (uint32_t)((wn*32 + nh*16 + ((lane >> 4) & 1)*8
                                     + (lane & 7))*ROWB + ((lane >> 3) & 1)*16);

    float rmv[2][2] = {{CUDART_INF_F, CUDART_INF_F},{CUDART_INF_F, CUDART_INF_F}};

    for(int ch=0; ch<NCHUNK; ++ch){
        const int buf = ch & 1;
        const int k0 = ch*CHUNK_N;
        if(ch+1 < NCHUNK){
            const __half* src = g_embf + (size_t)(ch+1)*CHUNK_N*CDIM;
            const uint32_t bdst = sb + OFF_BS + (uint32_t)((buf^1)*BS_BUF);
            #pragma unroll
            for(int i=0;i<8;++i){
                int seg = tid + i*NTHREADS;
                int n = seg >> 5, c16 = seg & 31;
                CP_ASYNC16(bdst + (uint32_t)(n*ROWB + c16*16),
                           src + (size_t)n*CDIM + c16*8);
            }
        }
        CP_COMMIT();
        CP_WAIT1();
        __syncthreads();

        // ---- GEMM: 32m x 32n per warp, K=256, f16 accumulate ----
        uint32_t acc[2][4][2];
        #pragma unroll
        for(int mt=0;mt<2;++mt)
            #pragma unroll
            for(int nt=0;nt<4;++nt){ acc[mt][nt][0] = 0u; acc[mt][nt][1] = 0u; }

        const uint32_t boff = (uint32_t)(buf*BS_BUF);
        #pragma unroll 4
        for(int ks=0; ks<16; ++ks){
            const uint32_t koff = (uint32_t)(ks*32);
            uint32_t a[2][4], bq[2][4];
            LDM_X4(a[0][0],a[0][1],a[0][2],a[0][3], a_base[0] + koff);
            LDM_X4(a[1][0],a[1][1],a[1][2],a[1][3], a_base[1] + koff);
            LDM_X4(bq[0][0],bq[0][1],bq[0][2],bq[0][3], b_base[0] + boff + koff);
            LDM_X4(bq[1][0],bq[1][1],bq[1][2],bq[1][3], b_base[1] + boff + koff);
            #pragma unroll
            for(int mt=0;mt<2;++mt)
                #pragma unroll
                for(int nt=0;nt<4;++nt)
                    MMA_F16ACC(acc[mt][nt][0], acc[mt][nt][1],
                               a[mt][0],a[mt][1],a[mt][2],a[mt][3],
                               bq[nt>>1][(nt&1)*2], bq[nt>>1][(nt&1)*2+1]);
        }

        // ---- phase a: d = en + DSCALE*S, chunk min, record-improve atomic ----
        float en0[4], en1[4];
        #pragma unroll
        for(int nt=0;nt<4;++nt){
            int nb = k0 + wn*32 + nt*8 + 2*t4;
            en0[nt] = __ldg(&g_enorm[nb]); en1[nt] = __ldg(&g_enorm[nb+1]);
        }
        float dv[2][4][4];
        float cmin[2][2];
        #pragma unroll
        for(int mt=0;mt<2;++mt)
            #pragma unroll
            for(int h=0;h<2;++h){
                float cm = CUDART_INF_F;
                #pragma unroll
                for(int nt=0;nt<4;++nt){
                    float2 p = __half22float2(*(__half2*)&acc[mt][nt][h]);
                    float d0 = __fmaf_rn(DSCALE, p.x, en0[nt]);
                    float d1 = __fmaf_rn(DSCALE, p.y, en1[nt]);
                    dv[mt][nt][2*h] = d0; dv[mt][nt][2*h+1] = d1;
                    if(d0 < cm) cm = d0;
                    if(d1 < cm) cm = d1;
                }
                cmin[mt][h] = cm;
                if(cm < rmv[mt][h]){
                    rmv[mt][h] = cm;
                    atomicMin(&s_min[wm*32 + mt*16 + g + h*8], fkey(cm));
                }
            }
        __syncthreads();

        // ---- phase b: push candidates within margin ----
        #pragma unroll
        for(int mt=0;mt<2;++mt)
            #pragma unroll
            for(int h=0;h<2;++h){
                int m = wm*32 + mt*16 + g + h*8;
                float thr = funkey(s_min[m]) + MARGIN;
                if(cmin[mt][h] <= thr){
                    #pragma unroll
                    for(int nt=0;nt<4;++nt){
                        #pragma unroll
                        for(int q=0;q<2;++q){
                            float d = dv[mt][nt][2*h+q];
                            if(d <= thr){
                                int slot = atomicAdd(&s_cnt[m], 1);
                                if(slot < CAP)
                                    s_cand[m*CAP + slot] =
                                        (unsigned short)(k0 + wn*32 + nt*8 + 2*t4 + q);
                            }
                        }
                    }
                }
            }
    }
    __syncthreads();

    // ---- reload exact fp32 z tile into freed A/B smem ----
    float* zf = (float*)smem;
    #pragma unroll
    for(int i=0;i<16;++i){
        int v = tid + i*NTHREADS;
        int c = v >> 5, m4 = (v & 31)*4;
        float4 q = *(const float4*)(zb + (size_t)c*HWDIM + m4);
        zf[(m4+0)*257 + c] = q.x; zf[(m4+1)*257 + c] = q.y;
        zf[(m4+2)*257 + c] = q.z; zf[(m4+3)*257 + c] = q.w;
    }
    __syncthreads();

    // ---- exact fp32 rescore (serial-FMA rounding == reference path) ----
    int* s_idx = (int*)(smem + OFF_SMIN);    // s_min dead after loop
    if(tid < 128){
        float zn = 0.f;
        #pragma unroll 8
        for(int c=0;c<CDIM;++c){
            float v = zf[tid*257 + c];
            zn = __fmaf_rn(v, v, zn);
        }
        int cn = s_cnt[tid]; if(cn > CAP) cn = CAP;
        float best = CUDART_INF_F; int bi = 0x7FFFFFFF;
        for(int i=0;i<cn;++i){
            int k = (int)s_cand[tid*CAP + i];
            const float* er = emb + (size_t)k*CDIM;
            float acc2 = 0.f;
            #pragma unroll 8
            for(int c=0;c<CDIM;++c)
                acc2 = __fmaf_rn(zf[tid*257 + c], er[c], acc2);
            float dd = __fsub_rn(__fadd_rn(zn, g_enorm[k]), __fmul_rn(2.f, acc2));
            if(dd < best || (dd == best && k < bi)){ best = dd; bi = k; }
        }
        s_idx[tid] = bi;
    }
    __syncthreads();

    // ---- fused outputs ----
    {
        const int m = tid & 127;
        const int cq = tid >> 7;                 // 0..3
        const int idxm = s_idx[m];
        #pragma unroll 2
        for(int i=0;i<64;++i){
            int c = 4*i + cq;
            float e  = __ldg(&emb[(size_t)idxm*CDIM + c]);
            float zv = zf[m*257 + c];
            float dq = __fsub_rn(e, zv);
            float zq = __fadd_rn(zv, dq);
            float d2 = __fmul_rn(dq, dq);
            float loss = __fadd_rn(__fmul_rn(0.25f, d2), d2);
            if(zq_off >= 0)
                out[(size_t)zq_off + (size_t)b*(CDIM*HWDIM) + (size_t)c*HWDIM + hw0 + m] = zq;
            zf[m*257 + c] = loss;
        }
    }
    __syncthreads();

    if(loss_off >= 0){
        const int c = tid & 255;
        const int mh = tid >> 8;                 // 0..1
        #pragma unroll 4
        for(int j=0;j<64;++j){
            int mm = 2*j + mh;
            out[(size_t)loss_off + (size_t)(m0+mm)*CDIM + c] = zf[mm*257 + c];
        }
    }
    if(idx_off >= 0 && tid < 128)
        out[(size_t)idx_off + m0 + tid] = (float)s_idx[tid];
}

extern "C" void kernel_launch(void* const* d_in, const int* in_sizes, int n_in,
                              void* d_out, int out_size){
    const float* z   = (const float*)d_in[0];
    const float* emb = (const float*)d_in[1];
    if(n_in >= 2 && in_sizes[0] == K_CODES*CDIM && in_sizes[1] == ZQ_ELEMS){
        z = (const float*)d_in[1]; emb = (const float*)d_in[0];
    }
    float* out = (float*)d_out;

    int zq_off=-1, loss_off=-1, idx_off=-1;
    if(out_size == 2*ZQ_ELEMS + IX_ELEMS){ zq_off=0; loss_off=ZQ_ELEMS; idx_off=2*ZQ_ELEMS; }
    else if(out_size == 2*ZQ_ELEMS){ zq_off=0; loss_off=ZQ_ELEMS; }
    else if(out_size == ZQ_ELEMS + IX_ELEMS){ zq_off=0; idx_off=ZQ_ELEMS; }
    else if(out_size == ZQ_ELEMS){ zq_off=0; }
    else if(out_size == IX_ELEMS){ idx_off=0; }
    else{
        int rem = out_size;
        if(rem >= ZQ_ELEMS){ zq_off=0; rem -= ZQ_ELEMS; }
        if(rem >= ZQ_ELEMS){ loss_off=ZQ_ELEMS; rem -= ZQ_ELEMS; }
        if(rem >= IX_ELEMS){ idx_off = out_size - IX_ELEMS; }
    }

    prep_kernel<<<K_CODES/256, 256>>>(emb);

    cudaFuncSetAttribute(vq_main, cudaFuncAttributeMaxDynamicSharedMemorySize, SMEM_TOTAL);
    vq_main<<<N_TOK/TILE_M, NTHREADS, SMEM_TOTAL>>>(z, emb, out, zq_off, loss_off, idx_off);
}